// round 16
// baseline (speedup 1.0000x reference)
#include <cuda_runtime.h>
#include <cuda_bf16.h>

// LinearSpline activation, division-free, channel-folded:
//   t  = x * (s[c]*6.25f)                 (6.25f == float(1/0.16), exact)
//   tc = clamp(t, -25.0f, 24.0f)          (== reference clip-then-divide)
//   ip = (int)floor(tc);  fr = t - ip     (fr from unclamped t, per reference)
//   out = fma(fr, C1-C0, C0)   where (C0,C1) = (c[z+ip]/s, c[z+ip+1]/s)
//
// R16 = R14 (best: __ldlu loads + __stcs stores, 768 thr x 2 CTAs/SM,
// 13KB table, in-place lean chain, ILP2 grid-stride) with the grid sized
// for GB300's **152** SMs (B300_MICROARCH GB300 delta), not 148. Every
// prior round under-filled 8 SMs by one CTA (296 CTAs on 152 SMs), taxing
// the whole kernel ~2.7%. blocks = 152*2 = 304.

#define NUM_ACT 64
#define SIZE    51
#define TABLE   (NUM_ACT * SIZE)   // 3264

__global__ __launch_bounds__(768, 2)
void linear_spline_kernel(const float4* __restrict__ x,
                          const float*  __restrict__ coef,
                          const float*  __restrict__ scale,
                          float4*       __restrict__ out,
                          int n4)
{
    __shared__ float sc[TABLE + 1];     // c[i]/s[c], 13.3 KB (+1 pad for v4 fill)
    __shared__ float s625[NUM_ACT];     // s[c] * 6.25f
    __shared__ float srs[NUM_ACT];      // 1/s[c]

    // One division per channel, not per table entry.
    if (threadIdx.x < NUM_ACT) {
        float s = scale[threadIdx.x];
        srs[threadIdx.x]  = 1.0f / s;        // exact for s==1
        s625[threadIdx.x] = s * 6.25f;       // exact for s==1
    }
    __syncthreads();

    // Vectorized table load: 816 float4 = 3264 floats.
    {
        const float4* c4 = (const float4*)coef;
        for (int q = threadIdx.x; q < TABLE / 4; q += 768) {
            float4 v = c4[q];
            int i0 = q * 4;
            sc[i0]     = v.x * srs[(i0)     / SIZE];
            sc[i0 + 1] = v.y * srs[(i0 + 1) / SIZE];
            sc[i0 + 2] = v.z * srs[(i0 + 2) / SIZE];
            sc[i0 + 3] = v.w * srs[(i0 + 3) / SIZE];
        }
    }
    __syncthreads();

    const int stride = gridDim.x * blockDim.x;
    int i = blockIdx.x * blockDim.x + threadIdx.x;

    // ~10 warp-ops + 2 LDS.32 per element; result overwrites the input
    // component to keep the live set at 8 floats. Max idx = 63*51+49+1 = 3263.
    #define ELEM(v, zk_, sg_) {                          \
        float t  = (v) * (sg_);                          \
        float tc = fminf(fmaxf(t, -25.0f), 24.0f);       \
        int   ip = __float2int_rd(tc);                   \
        float fr = t - (float)ip;                        \
        int p = (zk_) + ip;                              \
        float c0 = sc[p];                                \
        float c1 = sc[p + 1];                            \
        (v) = fmaf(fr, c1 - c0, c0); }

    // ILP=2: two independent LDG.128 in flight before any dependent compute.
    for (; i + stride < n4; i += 2 * stride) {
        const int j = i + stride;
        float4 xa = __ldlu(&x[i]);   // last-use: evict-first, free fill slots early
        float4 xb = __ldlu(&x[j]);

        const int ca = (i >> 12) & (NUM_ACT - 1);   // 4096 float4 per channel
        const int cb = (j >> 12) & (NUM_ACT - 1);
        const float sga = s625[ca];
        const float sgb = s625[cb];
        const int zka = ca * SIZE + SIZE / 2;
        const int zkb = cb * SIZE + SIZE / 2;

        ELEM(xa.x, zka, sga)
        ELEM(xa.y, zka, sga)
        ELEM(xa.z, zka, sga)
        ELEM(xa.w, zka, sga)
        ELEM(xb.x, zkb, sgb)
        ELEM(xb.y, zkb, sgb)
        ELEM(xb.z, zkb, sgb)
        ELEM(xb.w, zkb, sgb)

        __stcs(&out[i], xa);    // evict-first write stream
        __stcs(&out[j], xb);
    }
    // tail
    if (i < n4) {
        float4 xv = __ldlu(&x[i]);
        const int c = (i >> 12) & (NUM_ACT - 1);
        const float sg = s625[c];
        const int zk = c * SIZE + SIZE / 2;
        ELEM(xv.x, zk, sg)
        ELEM(xv.y, zk, sg)
        ELEM(xv.z, zk, sg)
        ELEM(xv.w, zk, sg)
        __stcs(&out[i], xv);
    }
    #undef ELEM
}

extern "C" void kernel_launch(void* const* d_in, const int* in_sizes, int n_in,
                              void* d_out, int out_size)
{
    const float* x     = (const float*)d_in[0];
    const float* coef  = (const float*)d_in[1];
    const float* scale = (const float*)d_in[2];
    float* out         = (float*)d_out;

    const int n  = in_sizes[0];   // 33,554,432
    const int n4 = n / 4;         // 8,388,608

    const int threads = 768;
    const int blocks  = 152 * 2;  // GB300 has 152 SMs: 2 CTAs on EVERY SM

    linear_spline_kernel<<<blocks, threads>>>(
        (const float4*)x, coef, scale, (float4*)out, n4);
}

// round 17
// speedup vs baseline: 1.0165x; 1.0165x over previous
#include <cuda_runtime.h>
#include <cuda_bf16.h>

// LinearSpline activation, division-free, channel-folded:
//   t  = x * (s[c]*6.25f)                 (6.25f == float(1/0.16), exact)
//   tc = clamp(t, -25.0f, 24.0f)          (== reference clip-then-divide)
//   ip = (int)floor(tc);  fr = t - ip     (fr from unclamped t, per reference)
//   out = fma(fr, C1-C0, C0)   where (C0,C1) = (c[z+ip]/s, c[z+ip+1]/s)
//
// R17 = R16 (ncu-best: __ldlu + __stcs, 768 thr x 2 CTAs on all 152 SMs,
// 13KB table, in-place lean chain, ILP2 grid-stride) + incremental channel
// arithmetic: stride = 304*768 = 57*4096 is an exact multiple of the
// per-channel float4 count, so channel(j) = (channel(i)+57)&63 and the
// per-trip channel advance is +114 = +50 (mod 64). The two (i>>12)&63
// chains per trip collapse to IADD+AND, off the LDS address critical path.

#define NUM_ACT 64
#define SIZE    51
#define TABLE   (NUM_ACT * SIZE)   // 3264

__global__ __launch_bounds__(768, 2)
void linear_spline_kernel(const float4* __restrict__ x,
                          const float*  __restrict__ coef,
                          const float*  __restrict__ scale,
                          float4*       __restrict__ out,
                          int n4)
{
    __shared__ float sc[TABLE + 1];     // c[i]/s[c], 13.3 KB (+1 pad for v4 fill)
    __shared__ float s625[NUM_ACT];     // s[c] * 6.25f
    __shared__ float srs[NUM_ACT];      // 1/s[c]

    // One division per channel, not per table entry.
    if (threadIdx.x < NUM_ACT) {
        float s = scale[threadIdx.x];
        srs[threadIdx.x]  = 1.0f / s;        // exact for s==1
        s625[threadIdx.x] = s * 6.25f;       // exact for s==1
    }
    __syncthreads();

    // Vectorized table load: 816 float4 = 3264 floats.
    {
        const float4* c4 = (const float4*)coef;
        for (int q = threadIdx.x; q < TABLE / 4; q += 768) {
            float4 v = c4[q];
            int i0 = q * 4;
            sc[i0]     = v.x * srs[(i0)     / SIZE];
            sc[i0 + 1] = v.y * srs[(i0 + 1) / SIZE];
            sc[i0 + 2] = v.z * srs[(i0 + 2) / SIZE];
            sc[i0 + 3] = v.w * srs[(i0 + 3) / SIZE];
        }
    }
    __syncthreads();

    const int stride = gridDim.x * blockDim.x;      // 233,472 = 57 * 4096
    int i = blockIdx.x * blockDim.x + threadIdx.x;

    // Incremental channel tracking: stride is a multiple of 4096 (the
    // per-channel float4 count), so channels advance deterministically.
    int ca = (i >> 12) & (NUM_ACT - 1);

    // ~10 warp-ops + 2 LDS.32 per element; result overwrites the input
    // component to keep the live set at 8 floats. Max idx = 63*51+49+1 = 3263.
    #define ELEM(v, zk_, sg_) {                          \
        float t  = (v) * (sg_);                          \
        float tc = fminf(fmaxf(t, -25.0f), 24.0f);       \
        int   ip = __float2int_rd(tc);                   \
        float fr = t - (float)ip;                        \
        int p = (zk_) + ip;                              \
        float c0 = sc[p];                                \
        float c1 = sc[p + 1];                            \
        (v) = fmaf(fr, c1 - c0, c0); }

    // ILP=2: two independent LDG.128 in flight before any dependent compute.
    for (; i + stride < n4; i += 2 * stride) {
        const int j = i + stride;
        float4 xa = __ldlu(&x[i]);   // last-use: evict-first, free fill slots early
        float4 xb = __ldlu(&x[j]);

        const int cb = (ca + 57) & (NUM_ACT - 1);   // stride = 57 channels
        const float sga = s625[ca];
        const float sgb = s625[cb];
        const int zka = ca * SIZE + SIZE / 2;
        const int zkb = cb * SIZE + SIZE / 2;

        ELEM(xa.x, zka, sga)
        ELEM(xa.y, zka, sga)
        ELEM(xa.z, zka, sga)
        ELEM(xa.w, zka, sga)
        ELEM(xb.x, zkb, sgb)
        ELEM(xb.y, zkb, sgb)
        ELEM(xb.z, zkb, sgb)
        ELEM(xb.w, zkb, sgb)

        __stcs(&out[i], xa);    // evict-first write stream
        __stcs(&out[j], xb);

        ca = (ca + 114) & (NUM_ACT - 1);            // advance 2 trips = 114 ch
    }
    // tail
    if (i < n4) {
        float4 xv = __ldlu(&x[i]);
        const float sg = s625[ca];
        const int zk = ca * SIZE + SIZE / 2;
        ELEM(xv.x, zk, sg)
        ELEM(xv.y, zk, sg)
        ELEM(xv.z, zk, sg)
        ELEM(xv.w, zk, sg)
        __stcs(&out[i], xv);
    }
    #undef ELEM
}

extern "C" void kernel_launch(void* const* d_in, const int* in_sizes, int n_in,
                              void* d_out, int out_size)
{
    const float* x     = (const float*)d_in[0];
    const float* coef  = (const float*)d_in[1];
    const float* scale = (const float*)d_in[2];
    float* out         = (float*)d_out;

    const int n  = in_sizes[0];   // 33,554,432
    const int n4 = n / 4;         // 8,388,608

    const int threads = 768;
    const int blocks  = 152 * 2;  // all 152 GB300 SMs; 304*768 = 57*4096
                                  // (divisible by the channel size -> the
                                  //  incremental channel trick is exact)

    linear_spline_kernel<<<blocks, threads>>>(
        (const float4*)x, coef, scale, (float4*)out, n4);
}